// round 1
// baseline (speedup 1.0000x reference)
#include <cuda_runtime.h>

// Conv2D valid cross-correlation: x[4096,4096] (fp32) * w[15,15] + bias -> out[4082,4082]
//
// Strategy: fp32 packed-pair FFMA2 (fma.rn.f32x2, sm_100+ only, unreachable from
// plain C++) with smem input tiling and register row-sliding.
//   - block = 256 threads, output tile 128(x) x 32(y)
//   - thread = 8(x) x 2(y) outputs held as 8 f32x2 accumulators
//   - per input row: 6x LDS.128 -> pack even- and odd-aligned f32x2 copies once,
//     then 2(ry) x 15(kx) x 4(pair) = 120 FFMA2 with zero per-use packing
//   - weights pre-duplicated (w,w) into smem as 8-byte entries -> LDS.64 broadcast

#define Hd 4096
#define Wd 4096
#define KHd 15
#define KWd 15
#define OHd (Hd - KHd + 1)   // 4082
#define OWd (Wd - KWd + 1)   // 4082

#define BXo 128              // block output tile x
#define BYo 32               // block output tile y
#define TILE_ROWS (BYo + KHd - 1)   // 46
#define SSTR 144             // smem row stride in floats (>= BXo + 14 = 142, 16B-aligned)

__device__ __forceinline__ unsigned long long pack2(float lo, float hi) {
    unsigned long long r;
    asm("mov.b64 %0, {%1, %2};" : "=l"(r) : "f"(lo), "f"(hi));
    return r;
}

__device__ __forceinline__ unsigned long long fma2(unsigned long long a,
                                                   unsigned long long b,
                                                   unsigned long long c) {
    unsigned long long d;
    asm("fma.rn.f32x2 %0, %1, %2, %3;" : "=l"(d) : "l"(a), "l"(b), "l"(c));
    return d;
}

// One ky-row of the stencil applied to 4 output pairs.
__device__ __forceinline__ void conv_row(unsigned long long acc[4],
                                         const unsigned long long* __restrict__ sw2,
                                         const unsigned long long even[11],
                                         const unsigned long long odd[10]) {
#pragma unroll
    for (int kx = 0; kx < KWd; ++kx) {
        unsigned long long w2 = sw2[kx];
#pragma unroll
        for (int p = 0; p < 4; ++p) {
            unsigned long long v = (kx & 1) ? odd[((kx - 1) >> 1) + p]
                                            : even[(kx >> 1) + p];
            acc[p] = fma2(v, w2, acc[p]);
        }
    }
}

// Load 24 floats of one smem row into registers and pack both pair alignments.
__device__ __forceinline__ void load_row(const float* __restrict__ srow,
                                         unsigned long long even[11],
                                         unsigned long long odd[10]) {
    float c[24];
#pragma unroll
    for (int i = 0; i < 6; ++i) {
        float4 v = ((const float4*)srow)[i];
        c[4 * i + 0] = v.x;
        c[4 * i + 1] = v.y;
        c[4 * i + 2] = v.z;
        c[4 * i + 3] = v.w;
    }
#pragma unroll
    for (int j = 0; j < 11; ++j) even[j] = pack2(c[2 * j], c[2 * j + 1]);
#pragma unroll
    for (int j = 0; j < 10; ++j) odd[j] = pack2(c[2 * j + 1], c[2 * j + 2]);
}

__global__ __launch_bounds__(256, 2)
void conv2d_f32x2_kernel(const float* __restrict__ x,
                         const float* __restrict__ wt,
                         const float* __restrict__ bias,
                         float* __restrict__ out) {
    __shared__ float s_in[TILE_ROWS * SSTR];
    __shared__ unsigned long long s_w2[KHd * KWd];

    const int tid = threadIdx.x;
    const int tx0 = blockIdx.x * BXo;   // input & output x base of this block
    const int ty0 = blockIdx.y * BYo;   // input & output y base of this block

    // Pre-duplicate weights (w, w) for FFMA2 broadcast via LDS.64.
    if (tid < KHd * KWd) {
        float w = wt[tid];
        s_w2[tid] = pack2(w, w);
    }

    // Stage input tile (46 rows x 144 cols) with float4 loads; zero-pad OOB.
    for (int s = tid; s < TILE_ROWS * 36; s += 256) {
        int rr = s / 36;
        int cc = (s - rr * 36) * 4;
        int gy = ty0 + rr;
        int gx = tx0 + cc;
        float4 v;
        if (gy < Hd && gx + 3 < Wd) {
            v = *(const float4*)(x + (size_t)gy * Wd + gx);
        } else {
            v.x = (gy < Hd && gx + 0 < Wd) ? x[(size_t)gy * Wd + gx + 0] : 0.f;
            v.y = (gy < Hd && gx + 1 < Wd) ? x[(size_t)gy * Wd + gx + 1] : 0.f;
            v.z = (gy < Hd && gx + 2 < Wd) ? x[(size_t)gy * Wd + gx + 2] : 0.f;
            v.w = (gy < Hd && gx + 3 < Wd) ? x[(size_t)gy * Wd + gx + 3] : 0.f;
        }
        *(float4*)&s_in[rr * SSTR + cc] = v;
    }
    __syncthreads();

    const int tx = tid & 15;
    const int ty = tid >> 4;
    const int oxl = tx * 8;   // local output x base (8 outputs)
    const int oyl = ty * 2;   // local output y base (2 outputs)

    const float b = bias[0];
    const unsigned long long b2 = pack2(b, b);
    unsigned long long acc0[4] = {b2, b2, b2, b2};
    unsigned long long acc1[4] = {b2, b2, b2, b2};

    unsigned long long even[11], odd[10];

    // r = 0: contributes only to output row 0 (ky = 0)
    load_row(&s_in[(oyl + 0) * SSTR + oxl], even, odd);
    conv_row(acc0, &s_w2[0], even, odd);

    // r = 1..14: contributes to both output rows (ky = r and r-1)
#pragma unroll 1
    for (int r = 1; r <= 14; ++r) {
        load_row(&s_in[(oyl + r) * SSTR + oxl], even, odd);
        conv_row(acc0, &s_w2[r * KWd], even, odd);
        conv_row(acc1, &s_w2[(r - 1) * KWd], even, odd);
    }

    // r = 15: contributes only to output row 1 (ky = 14)
    load_row(&s_in[(oyl + 15) * SSTR + oxl], even, odd);
    conv_row(acc1, &s_w2[14 * KWd], even, odd);

    // Store: pairs are even-aligned and OW (4082) is even -> pairs never straddle.
    const int oxg = tx0 + oxl;
#pragma unroll
    for (int ry = 0; ry < 2; ++ry) {
        int oy = ty0 + oyl + ry;
        if (oy < OHd) {
            const unsigned long long* accp = ry ? acc1 : acc0;
            float* orow = out + (size_t)oy * OWd;
#pragma unroll
            for (int p = 0; p < 4; ++p) {
                int ox = oxg + 2 * p;
                if (ox < OWd) {
                    *(unsigned long long*)(orow + ox) = accp[p];
                }
            }
        }
    }
}

extern "C" void kernel_launch(void* const* d_in, const int* in_sizes, int n_in,
                              void* d_out, int out_size) {
    const float* x    = (const float*)d_in[0];
    const float* wt   = (const float*)d_in[1];
    const float* bias = (const float*)d_in[2];
    float* out        = (float*)d_out;

    dim3 grid((OWd + BXo - 1) / BXo, (OHd + BYo - 1) / BYo);  // (32, 128)
    conv2d_f32x2_kernel<<<grid, 256>>>(x, wt, bias, out);
}